// round 1
// baseline (speedup 1.0000x reference)
#include <cuda_runtime.h>
#include <cstddef>

#define WORDS   1000000
#define EMB_D   64
#define KTH     4
#define BATCH   8192

// Graph-replay-safe scratch (no device allocation allowed).
__device__ float g_wsum[EMB_D];
__device__ float g_bsum[KTH];
__device__ int   g_correct;

__global__ void prank_zero_kernel() {
    int t = threadIdx.x;
    if (t < EMB_D) g_wsum[t] = 0.0f;
    if (t < KTH)   g_bsum[t] = 0.0f;
    if (t == 0)    g_correct = 0;
}

// One warp per target. Lane l owns dims (2l, 2l+1).
__global__ void prank_reduce_kernel(const float* __restrict__ embed,
                                    const float* __restrict__ bias,
                                    const int*   __restrict__ ctx_id,
                                    const int*   __restrict__ tgt,
                                    const int*   __restrict__ lab) {
    __shared__ float s_ctx[EMB_D];
    __shared__ float s_bias[KTH];
    __shared__ float s_w[8][EMB_D];   // up to 8 warps/block
    __shared__ float s_b[8][KTH];
    __shared__ int   s_c[8];

    const int tid = threadIdx.x;
    const int ctx = ctx_id[0];
    if (tid < EMB_D) s_ctx[tid]  = embed[(size_t)ctx * EMB_D + tid];
    if (tid < KTH)   s_bias[tid] = bias[(size_t)ctx * KTH + tid];
    __syncthreads();

    const int warp   = tid >> 5;
    const int lane   = tid & 31;
    const int nwarps = blockDim.x >> 5;
    const int gwarp  = blockIdx.x * nwarps + warp;
    const int twarps = gridDim.x * nwarps;

    const float2 c2 = reinterpret_cast<const float2*>(s_ctx)[lane];

    float wx = 0.0f, wy = 0.0f;
    float b0 = 0.0f, b1 = 0.0f, b2 = 0.0f, b3 = 0.0f;
    int corr = 0;

    for (int b = gwarp; b < BATCH; b += twarps) {
        const int t = tgt[b];
        const float2 e2 =
            reinterpret_cast<const float2*>(embed + (size_t)t * EMB_D)[lane];
        float p = e2.x * c2.x + e2.y * c2.y;
        #pragma unroll
        for (int o = 16; o; o >>= 1) p += __shfl_xor_sync(0xffffffffu, p, o);
        const float dot = p;

        const int   L    = lab[b];
        const float labf = (float)L;

        float taurow = 0.0f;
        int   plabel = KTH + 1;
        float tj[KTH];
        #pragma unroll
        for (int j = KTH - 1; j >= 0; j--) {
            const float db = dot - s_bias[j];
            if (db <= 0.0f) plabel = j + 1;     // descending j -> first nonpos index
            const float yt  = (j < L) ? 1.0f : -1.0f;
            const float tau = (db * yt > 0.0f) ? 0.0f : labf;
            tj[j] = tau;
            taurow += tau;
        }
        if (lane == 0) {
            b0 += tj[0]; b1 += tj[1]; b2 += tj[2]; b3 += tj[3];
            if (plabel == L) corr++;
        }
        wx += taurow * e2.x;
        wy += taurow * e2.y;
    }

    s_w[warp][2 * lane]     = wx;
    s_w[warp][2 * lane + 1] = wy;
    if (lane == 0) {
        s_b[warp][0] = b0; s_b[warp][1] = b1; s_b[warp][2] = b2; s_b[warp][3] = b3;
        s_c[warp] = corr;
    }
    __syncthreads();

    if (tid < EMB_D) {
        float s = 0.0f;
        for (int w = 0; w < nwarps; w++) s += s_w[w][tid];
        atomicAdd(&g_wsum[tid], s);
    }
    if (tid < KTH) {
        float s = 0.0f;
        for (int w = 0; w < nwarps; w++) s += s_b[w][tid];
        atomicAdd(&g_bsum[tid], s);
    }
    if (tid == 0) {
        int s = 0;
        for (int w = 0; w < nwarps; w++) s += s_c[w];
        atomicAdd(&g_correct, s);
    }
}

// Patch the 68 updated elements + scalar accuracy (runs after the bulk copy).
__global__ void prank_finalize_kernel(const float* __restrict__ embed,
                                      const float* __restrict__ bias,
                                      const int*   __restrict__ ctx_id,
                                      float* __restrict__ out) {
    const int t   = threadIdx.x;
    const int ctx = ctx_id[0];
    const float invB = 1.0f / (float)BATCH;
    if (t == 0) out[0] = (float)g_correct * invB;
    if (t < EMB_D) {
        const size_t off = (size_t)ctx * EMB_D + t;
        out[1 + off] = embed[off] + g_wsum[t] * invB;
    }
    if (t < KTH) {
        const size_t off = (size_t)ctx * KTH + t;
        out[1 + (size_t)WORDS * EMB_D + off] = bias[off] - g_bsum[t] * invB;
    }
}

extern "C" void kernel_launch(void* const* d_in, const int* in_sizes, int n_in,
                              void* d_out, int out_size) {
    const float* in_embed = (const float*)d_in[0];
    const float* in_bias  = (const float*)d_in[1];
    const int*   ctx_id   = (const int*)d_in[2];
    const int*   tgt      = (const int*)d_in[3];
    const int*   lab      = (const int*)d_in[4];
    float* out = (float*)d_out;

    (void)n_in; (void)out_size;
    const size_t embed_elems = (size_t)WORDS * EMB_D;
    const size_t bias_elems  = (size_t)WORDS * KTH;

    prank_zero_kernel<<<1, 128>>>();
    prank_reduce_kernel<<<128, 256>>>(in_embed, in_bias, ctx_id, tgt, lab);

    // Bulk copy: out layout = [acc][new_embed][new_bias]
    cudaMemcpyAsync(out + 1, in_embed, embed_elems * sizeof(float),
                    cudaMemcpyDeviceToDevice, 0);
    cudaMemcpyAsync(out + 1 + embed_elems, in_bias, bias_elems * sizeof(float),
                    cudaMemcpyDeviceToDevice, 0);

    prank_finalize_kernel<<<1, 128>>>(in_embed, in_bias, ctx_id, out);
}

// round 2
// speedup vs baseline: 1.7942x; 1.7942x over previous
#include <cuda_runtime.h>
#include <cstddef>

#define WORDS   1000000
#define EMB_D   64
#define KTH     4
#define BATCH   8192

#define E_ELEMS   ((long)WORDS * EMB_D)          // 64,000,000
#define B_ELEMS   ((long)WORDS * KTH)            // 4,000,000
#define TOT_ELEMS (E_ELEMS + B_ELEMS)            // 68,000,000
#define K_CH      (TOT_ELEMS / 4)                // 17,000,000 float4 chunks
#define RB        64                             // reduce blocks
#define INVB      (1.0f / (float)BATCH)

// Per-block partials (always fully overwritten each launch -> graph-replay safe).
__device__ float g_pw[RB][EMB_D];
__device__ float g_pb[RB][KTH];
__device__ int   g_pc[RB];

// ---------------------------------------------------------------------------
// Reduce: one warp per group of targets; per-block partials, no atomics.
// ---------------------------------------------------------------------------
__global__ void prank_reduce_kernel(const float* __restrict__ embed,
                                    const float* __restrict__ bias,
                                    const int*   __restrict__ ctx_id,
                                    const int*   __restrict__ tgt,
                                    const int*   __restrict__ lab) {
    __shared__ float s_ctx[EMB_D];
    __shared__ float s_bias[KTH];
    __shared__ float s_w[8][EMB_D];
    __shared__ float s_b[8][KTH];
    __shared__ int   s_c[8];

    const int tid = threadIdx.x;
    const int ctx = __ldg(ctx_id);
    if (tid < EMB_D) s_ctx[tid]  = __ldg(embed + (size_t)ctx * EMB_D + tid);
    if (tid < KTH)   s_bias[tid] = __ldg(bias  + (size_t)ctx * KTH + tid);
    __syncthreads();

    const int warp   = tid >> 5;
    const int lane   = tid & 31;
    const int nwarps = blockDim.x >> 5;
    const int gwarp  = blockIdx.x * nwarps + warp;
    const int twarps = gridDim.x * nwarps;

    const float2 c2 = reinterpret_cast<const float2*>(s_ctx)[lane];

    float wx = 0.0f, wy = 0.0f;
    float b0 = 0.0f, b1 = 0.0f, b2 = 0.0f, b3 = 0.0f;
    int corr = 0;

    for (int b = gwarp; b < BATCH; b += twarps) {
        const int t = __ldg(tgt + b);
        const float2 e2 =
            reinterpret_cast<const float2*>(embed + (size_t)t * EMB_D)[lane];
        float p = e2.x * c2.x + e2.y * c2.y;
        #pragma unroll
        for (int o = 16; o; o >>= 1) p += __shfl_xor_sync(0xffffffffu, p, o);
        const float dot = p;

        const int   L    = __ldg(lab + b);
        const float labf = (float)L;

        float taurow = 0.0f;
        int   plabel = KTH + 1;
        float tj[KTH];
        #pragma unroll
        for (int j = KTH - 1; j >= 0; j--) {
            const float db = dot - s_bias[j];
            if (db <= 0.0f) plabel = j + 1;
            const float yt  = (j < L) ? 1.0f : -1.0f;
            const float tau = (db * yt > 0.0f) ? 0.0f : labf;
            tj[j] = tau;
            taurow += tau;
        }
        if (lane == 0) {
            b0 += tj[0]; b1 += tj[1]; b2 += tj[2]; b3 += tj[3];
            if (plabel == L) corr++;
        }
        wx += taurow * e2.x;
        wy += taurow * e2.y;
    }

    s_w[warp][2 * lane]     = wx;
    s_w[warp][2 * lane + 1] = wy;
    if (lane == 0) {
        s_b[warp][0] = b0; s_b[warp][1] = b1; s_b[warp][2] = b2; s_b[warp][3] = b3;
        s_c[warp] = corr;
    }
    __syncthreads();

    if (tid < EMB_D) {
        float s = 0.0f;
        #pragma unroll
        for (int w = 0; w < 8; w++) s += s_w[w][tid];
        g_pw[blockIdx.x][tid] = s;
    }
    if (tid < KTH) {
        float s = 0.0f;
        #pragma unroll
        for (int w = 0; w < 8; w++) s += s_b[w][tid];
        g_pb[blockIdx.x][tid] = s;
    }
    if (tid == 0) {
        int s = 0;
        #pragma unroll
        for (int w = 0; w < 8; w++) s += s_c[w];
        g_pc[blockIdx.x] = s;
    }
}

// ---------------------------------------------------------------------------
// Copy + finalize
// ---------------------------------------------------------------------------
__device__ __forceinline__ float load_src(long s,
                                          const float* __restrict__ emb,
                                          const float* __restrict__ bia) {
    return (s < E_ELEMS) ? __ldg(emb + s) : __ldg(bia + (s - E_ELEMS));
}

__device__ __forceinline__ float sum_w(int t) {
    float s = 0.0f;
    #pragma unroll 8
    for (int b = 0; b < RB; b++) s += g_pw[b][t];
    return s;
}
__device__ __forceinline__ float sum_b(int t) {
    float s = 0.0f;
    #pragma unroll 8
    for (int b = 0; b < RB; b++) s += g_pb[b][t];
    return s;
}

__global__ void __launch_bounds__(256)
prank_copy_finalize_kernel(const float* __restrict__ emb,
                           const float* __restrict__ bia,
                           const int*   __restrict__ ctx_id,
                           float* __restrict__ out) {
    const long gtid = (long)blockIdx.x * blockDim.x + threadIdx.x;
    const long k    = gtid + 1;                       // chunk index, writes out[4k..4k+4)
    const bool active = (k < K_CH);
    const long kk = active ? k : (K_CH - 1);          // clamp so whole warp converges
    const long s  = 4 * kk;                           // first "B" source element

    // Aligned float4 load of src[4k .. 4k+3] (a chunk never straddles E_ELEMS).
    const float4* p = (s < E_ELEMS)
        ? (reinterpret_cast<const float4*>(emb) + kk)
        : (reinterpret_cast<const float4*>(bia) + (kk - E_ELEMS / 4));
    const float4 B = __ldg(p);

    // Leading element src[4k-1]: neighbor lane's B.w, scalar load at warp head.
    float prevw = __shfl_up_sync(0xffffffffu, B.w, 1);
    if ((threadIdx.x & 31) == 0) prevw = load_src(s - 1, emb, bia);

    if (active) {
        float o[4] = {prevw, B.x, B.y, B.z};          // = src[4k-1 .. 4k+2]
        const long s0 = s - 1;

        const int  ctx   = __ldg(ctx_id);
        const long wbase = (long)ctx * EMB_D;
        const long bbase = E_ELEMS + (long)ctx * KTH;

        if (s0 <= wbase + (EMB_D - 1) && s0 + 3 >= wbase) {
            #pragma unroll
            for (int c = 0; c < 4; c++) {
                const long idx = s0 + c;
                if (idx >= wbase && idx < wbase + EMB_D)
                    o[c] += sum_w((int)(idx - wbase)) * INVB;
            }
        }
        if (s0 <= bbase + (KTH - 1) && s0 + 3 >= bbase) {
            #pragma unroll
            for (int c = 0; c < 4; c++) {
                const long idx = s0 + c;
                if (idx >= bbase && idx < bbase + KTH)
                    o[c] -= sum_b((int)(idx - bbase)) * INVB;
            }
        }
        reinterpret_cast<float4*>(out)[kk] =
            make_float4(o[0], o[1], o[2], o[3]);       // 16B-aligned store at out[4k]
    }

    if (gtid == 0) {
        const int  ctx   = __ldg(ctx_id);
        const long wbase = (long)ctx * EMB_D;
        const long bbase = E_ELEMS + (long)ctx * KTH;

        int c = 0;
        #pragma unroll 8
        for (int b = 0; b < RB; b++) c += g_pc[b];
        out[0] = (float)c * INVB;

        // Head: out[1..3] = src[0..2] (patched only if ctx == 0).
        #pragma unroll
        for (int j = 0; j < 3; j++) {
            float v = load_src(j, emb, bia);
            if (j >= wbase && j < wbase + EMB_D)
                v += sum_w(j - (int)wbase) * INVB;
            out[1 + j] = v;
        }
        // Tail: out[TOT] = src[TOT-1] (patched only if ctx == WORDS-1).
        {
            const long j = TOT_ELEMS - 1;
            float v = load_src(j, emb, bia);
            if (j >= bbase && j < bbase + KTH)
                v -= sum_b((int)(j - bbase)) * INVB;
            out[TOT_ELEMS] = v;
        }
    }
}

extern "C" void kernel_launch(void* const* d_in, const int* in_sizes, int n_in,
                              void* d_out, int out_size) {
    const float* in_embed = (const float*)d_in[0];
    const float* in_bias  = (const float*)d_in[1];
    const int*   ctx_id   = (const int*)d_in[2];
    const int*   tgt      = (const int*)d_in[3];
    const int*   lab      = (const int*)d_in[4];
    float* out = (float*)d_out;
    (void)n_in; (void)out_size; (void)in_sizes;

    prank_reduce_kernel<<<RB, 256>>>(in_embed, in_bias, ctx_id, tgt, lab);

    const long nthreads = K_CH - 1;                   // chunks k = 1 .. K_CH-1
    const int  blocks   = (int)((nthreads + 255) / 256);
    prank_copy_finalize_kernel<<<blocks, 256>>>(in_embed, in_bias, ctx_id, out);
}